// round 2
// baseline (speedup 1.0000x reference)
#include <cuda_runtime.h>
#include <cuda_bf16.h>

// Problem constants
#define BB 4
#define SS 2048
#define DD 1024
#define HH 16
#define HD 64
#define NTOK (BB*SS)          // 8192

// ---------------- scratch (device globals; no allocation) ----------------
__device__ float g_Q[BB*HH*SS*HD];     // [B,H,S,HD]
__device__ float g_K[BB*HH*SS*HD];
__device__ float g_V[BB*HH*SS*HD];
__device__ float g_ctx[NTOK*DD];       // [B,S,D]
__device__ float g_ln[NTOK*DD];        // [B,S,D]

// =========================================================================
// Dense GEMM tiles: 128x128x16, 256 threads, 8x8 per thread (4+4 split frags)
// =========================================================================
#define TM 128
#define TN 128
#define TK 16

// =========================================================================
// Kernel 1: fused QKV projection.  C = X @ W^T + b, scattered to [B,H,S,HD]
// =========================================================================
__global__ __launch_bounds__(256) void qkv_kernel(
    const float* __restrict__ X,
    const float* __restrict__ Wq, const float* __restrict__ bq,
    const float* __restrict__ Wk, const float* __restrict__ bk,
    const float* __restrict__ Wv, const float* __restrict__ bv)
{
    const float* W; const float* bias; float* out;
    if (blockIdx.z == 0)      { W = Wq; bias = bq; out = g_Q; }
    else if (blockIdx.z == 1) { W = Wk; bias = bk; out = g_K; }
    else                      { W = Wv; bias = bv; out = g_V; }

    __shared__ float As[TK][TM + 4];
    __shared__ float Bs[TK][TN + 4];

    const int t  = threadIdx.x;
    const int tx = t & 15;
    const int ty = t >> 4;
    const int m0 = blockIdx.x * TM;
    const int n0 = blockIdx.y * TN;

    float acc[8][8];
#pragma unroll
    for (int r = 0; r < 8; r++)
#pragma unroll
        for (int c = 0; c < 8; c++) acc[r][c] = 0.f;

    for (int k0 = 0; k0 < DD; k0 += TK) {
        // A tile: 128x16 = 512 float4; 2 per thread, stored transposed
#pragma unroll
        for (int i = 0; i < 2; i++) {
            int idx = t + i * 256;
            int row = idx >> 2, c4 = idx & 3;
            float4 v = *(const float4*)&X[(size_t)(m0 + row) * DD + k0 + c4 * 4];
            As[c4 * 4 + 0][row] = v.x;
            As[c4 * 4 + 1][row] = v.y;
            As[c4 * 4 + 2][row] = v.z;
            As[c4 * 4 + 3][row] = v.w;
        }
        // B tile: 128x16 = 512 float4; 2 per thread, stored transposed
#pragma unroll
        for (int i = 0; i < 2; i++) {
            int idx = t + i * 256;
            int row = idx >> 2, c4 = idx & 3;
            float4 v = *(const float4*)&W[(size_t)(n0 + row) * DD + k0 + c4 * 4];
            Bs[c4 * 4 + 0][row] = v.x;
            Bs[c4 * 4 + 1][row] = v.y;
            Bs[c4 * 4 + 2][row] = v.z;
            Bs[c4 * 4 + 3][row] = v.w;
        }
        __syncthreads();

#pragma unroll
        for (int k = 0; k < TK; k++) {
            float4 a0 = *(const float4*)&As[k][ty * 4];
            float4 a1 = *(const float4*)&As[k][64 + ty * 4];
            float4 b0 = *(const float4*)&Bs[k][tx * 4];
            float4 b1 = *(const float4*)&Bs[k][64 + tx * 4];
            float a[8] = {a0.x, a0.y, a0.z, a0.w, a1.x, a1.y, a1.z, a1.w};
            float b[8] = {b0.x, b0.y, b0.z, b0.w, b1.x, b1.y, b1.z, b1.w};
#pragma unroll
            for (int r = 0; r < 8; r++)
#pragma unroll
                for (int c = 0; c < 8; c++) acc[r][c] += a[r] * b[c];
        }
        __syncthreads();
    }

    // epilogue: write to [B,H,S,HD]; each 4-col frag sits inside one head
#pragma unroll
    for (int hn = 0; hn < 2; hn++) {
        int col = n0 + hn * 64 + tx * 4;
        int h = col >> 6;
        int d = col & 63;
        float4 bv4 = *(const float4*)&bias[col];
#pragma unroll
        for (int hm = 0; hm < 2; hm++) {
#pragma unroll
            for (int r = 0; r < 4; r++) {
                int m = m0 + hm * 64 + ty * 4 + r;
                int b = m >> 11;               // /S
                int s = m & (SS - 1);
                float4 res;
                res.x = acc[hm * 4 + r][hn * 4 + 0] + bv4.x;
                res.y = acc[hm * 4 + r][hn * 4 + 1] + bv4.y;
                res.z = acc[hm * 4 + r][hn * 4 + 2] + bv4.z;
                res.w = acc[hm * 4 + r][hn * 4 + 3] + bv4.w;
                *(float4*)&out[(((size_t)(b * HH + h) * SS) + s) * HD + d] = res;
            }
        }
    }
}

// =========================================================================
// Kernel 2: flash attention.  grid = (S/64, B*H), 256 threads.
// Q tile 64 rows; KV tiles of 64; online softmax; fp32 throughout.
// =========================================================================
#define ATT_SMEM_FLOATS (64*68 + 64*68 + 64*64 + 64*68 + 64)
#define ATT_SMEM_BYTES  (ATT_SMEM_FLOATS * 4)

__global__ __launch_bounds__(256) void attn_kernel(const float* __restrict__ mask)
{
    extern __shared__ float sm[];
    float* Qs = sm;                 // [64][68], d-major: Qs[d][q]
    float* Ks = Qs + 64 * 68;       // [64][68], d-major: Ks[d][kv]
    float* Vs = Ks + 64 * 68;       // [64][64], kv-major: Vs[kv][d]
    float* Ps = Vs + 64 * 64;       // [64][68], q-major:  Ps[q][kv]
    float* Ms = Ps + 64 * 68;       // [64] mask tile

    const int t  = threadIdx.x;
    const int tx = t & 15;
    const int ty = t >> 4;
    const int q0 = blockIdx.x * 64;
    const int bh = blockIdx.y;
    const int b  = bh >> 4;
    const int h  = bh & 15;

    const float* Qb = g_Q + ((size_t)bh * SS + q0) * HD;
    const float* Kb = g_K + (size_t)bh * SS * HD;
    const float* Vb = g_V + (size_t)bh * SS * HD;
    const float* mb = mask + (size_t)b * SS;

    // load Q tile transposed: Qs[d][q]
#pragma unroll
    for (int i = 0; i < 4; i++) {
        int idx = t + i * 256;
        int row = idx >> 4, d4 = idx & 15;
        float4 v = *(const float4*)&Qb[(size_t)row * HD + d4 * 4];
        Qs[(d4 * 4 + 0) * 68 + row] = v.x;
        Qs[(d4 * 4 + 1) * 68 + row] = v.y;
        Qs[(d4 * 4 + 2) * 68 + row] = v.z;
        Qs[(d4 * 4 + 3) * 68 + row] = v.w;
    }

    float m_i[4], l_i[4], o[4][4];
#pragma unroll
    for (int r = 0; r < 4; r++) {
        m_i[r] = -1e30f; l_i[r] = 0.f;
#pragma unroll
        for (int c = 0; c < 4; c++) o[r][c] = 0.f;
    }

    for (int j = 0; j < SS / 64; j++) {
        const int kv0 = j * 64;
        // load K transposed, V direct
#pragma unroll
        for (int i = 0; i < 4; i++) {
            int idx = t + i * 256;
            int row = idx >> 4, d4 = idx & 15;
            float4 v = *(const float4*)&Kb[(size_t)(kv0 + row) * HD + d4 * 4];
            Ks[(d4 * 4 + 0) * 68 + row] = v.x;
            Ks[(d4 * 4 + 1) * 68 + row] = v.y;
            Ks[(d4 * 4 + 2) * 68 + row] = v.z;
            Ks[(d4 * 4 + 3) * 68 + row] = v.w;
            float4 w = *(const float4*)&Vb[(size_t)(kv0 + row) * HD + d4 * 4];
            *(float4*)&Vs[row * 64 + d4 * 4] = w;
        }
        if (t < 64) Ms[t] = mb[kv0 + t];
        __syncthreads();

        // S = (Q K^T) * 0.125 + additive mask
        float s[4][4];
#pragma unroll
        for (int r = 0; r < 4; r++)
#pragma unroll
            for (int c = 0; c < 4; c++) s[r][c] = 0.f;

#pragma unroll 16
        for (int d = 0; d < 64; d++) {
            float4 q4 = *(const float4*)&Qs[d * 68 + ty * 4];
            float4 k4 = *(const float4*)&Ks[d * 68 + tx * 4];
            float qa[4] = {q4.x, q4.y, q4.z, q4.w};
            float ka[4] = {k4.x, k4.y, k4.z, k4.w};
#pragma unroll
            for (int r = 0; r < 4; r++)
#pragma unroll
                for (int c = 0; c < 4; c++) s[r][c] += qa[r] * ka[c];
        }

        float madd[4];
#pragma unroll
        for (int c = 0; c < 4; c++) madd[c] = (1.0f - Ms[tx * 4 + c]) * -10000.0f;

        // online softmax update (row groups share the 16-lane tx sub-warp)
#pragma unroll
        for (int r = 0; r < 4; r++) {
            float mx = -1e30f;
#pragma unroll
            for (int c = 0; c < 4; c++) {
                s[r][c] = s[r][c] * 0.125f + madd[c];
                mx = fmaxf(mx, s[r][c]);
            }
#pragma unroll
            for (int off = 1; off < 16; off <<= 1)
                mx = fmaxf(mx, __shfl_xor_sync(0xffffffffu, mx, off));
            float mnew = fmaxf(m_i[r], mx);
            float corr = __expf(m_i[r] - mnew);
            m_i[r] = mnew;
            float rs = 0.f;
#pragma unroll
            for (int c = 0; c < 4; c++) {
                s[r][c] = __expf(s[r][c] - mnew);
                rs += s[r][c];
            }
#pragma unroll
            for (int off = 1; off < 16; off <<= 1)
                rs += __shfl_xor_sync(0xffffffffu, rs, off);
            l_i[r] = l_i[r] * corr + rs;
#pragma unroll
            for (int c = 0; c < 4; c++) o[r][c] *= corr;
        }

        // stage P to smem: Ps[q][kv]
#pragma unroll
        for (int r = 0; r < 4; r++)
#pragma unroll
            for (int c = 0; c < 4; c++)
                Ps[(ty * 4 + r) * 68 + tx * 4 + c] = s[r][c];
        __syncthreads();

        // O += P @ V
#pragma unroll
        for (int kv = 0; kv < 64; kv += 4) {
            float4 vv0 = *(const float4*)&Vs[(kv + 0) * 64 + tx * 4];
            float4 vv1 = *(const float4*)&Vs[(kv + 1) * 64 + tx * 4];
            float4 vv2 = *(const float4*)&Vs[(kv + 2) * 64 + tx * 4];
            float4 vv3 = *(const float4*)&Vs[(kv + 3) * 64 + tx * 4];
#pragma unroll
            for (int r = 0; r < 4; r++) {
                float4 p4 = *(const float4*)&Ps[(ty * 4 + r) * 68 + kv];
                o[r][0] += p4.x * vv0.x + p4.y * vv1.x + p4.z * vv2.x + p4.w * vv3.x;
                o[r][1] += p4.x * vv0.y + p4.y * vv1.y + p4.z * vv2.y + p4.w * vv3.y;
                o[r][2] += p4.x * vv0.z + p4.y * vv1.z + p4.z * vv2.z + p4.w * vv3.z;
                o[r][3] += p4.x * vv0.w + p4.y * vv1.w + p4.z * vv2.w + p4.w * vv3.w;
            }
        }
        __syncthreads();
    }

    // epilogue: ctx[b][s][h*64+d]
#pragma unroll
    for (int r = 0; r < 4; r++) {
        float inv = 1.0f / l_i[r];
        int srow = q0 + ty * 4 + r;
        float4 res;
        res.x = o[r][0] * inv;
        res.y = o[r][1] * inv;
        res.z = o[r][2] * inv;
        res.w = o[r][3] * inv;
        *(float4*)&g_ctx[((size_t)(b * SS + srow) * DD) + h * HD + tx * 4] = res;
    }
}

// =========================================================================
// Kernel 3: residual add + LayerNorm (two-pass), one block per row
// =========================================================================
__device__ __forceinline__ float block_reduce_sum(float v, float* sred)
{
    int t = threadIdx.x;
#pragma unroll
    for (int o = 16; o > 0; o >>= 1) v += __shfl_xor_sync(0xffffffffu, v, o);
    if ((t & 31) == 0) sred[t >> 5] = v;
    __syncthreads();
    if (t < 32) {
        float x = (t < 8) ? sred[t] : 0.f;
#pragma unroll
        for (int o = 4; o > 0; o >>= 1) x += __shfl_xor_sync(0xffffffffu, x, o);
        if (t == 0) sred[0] = x;
    }
    __syncthreads();
    float r = sred[0];
    __syncthreads();
    return r;
}

__global__ __launch_bounds__(256) void ln_kernel(
    const float* __restrict__ resid,
    const float* __restrict__ gamma, const float* __restrict__ beta)
{
    __shared__ float sred[8];
    const int row = blockIdx.x;
    const int t = threadIdx.x;

    float4 c4 = *(const float4*)&g_ctx[(size_t)row * DD + t * 4];
    float4 r4 = *(const float4*)&resid[(size_t)row * DD + t * 4];
    float x0 = c4.x + r4.x, x1 = c4.y + r4.y, x2 = c4.z + r4.z, x3 = c4.w + r4.w;

    float mu = block_reduce_sum(x0 + x1 + x2 + x3, sred) * (1.0f / DD);
    float d0 = x0 - mu, d1 = x1 - mu, d2 = x2 - mu, d3 = x3 - mu;
    float var = block_reduce_sum(d0 * d0 + d1 * d1 + d2 * d2 + d3 * d3, sred) * (1.0f / DD);
    float rstd = rsqrtf(var + 1e-5f);

    float4 g4 = *(const float4*)&gamma[t * 4];
    float4 b4 = *(const float4*)&beta[t * 4];
    float4 res;
    res.x = d0 * rstd * g4.x + b4.x;
    res.y = d1 * rstd * g4.y + b4.y;
    res.z = d2 * rstd * g4.z + b4.z;
    res.w = d3 * rstd * g4.w + b4.w;
    *(float4*)&g_ln[(size_t)row * DD + t * 4] = res;
}

// =========================================================================
// Kernel 4: output GEMM + bias + LeakyReLU + mask
// =========================================================================
__global__ __launch_bounds__(256) void out_kernel(
    const float* __restrict__ Wo, const float* __restrict__ bo,
    const float* __restrict__ mask, float* __restrict__ out)
{
    __shared__ float As[TK][TM + 4];
    __shared__ float Bs[TK][TN + 4];

    const int t  = threadIdx.x;
    const int tx = t & 15;
    const int ty = t >> 4;
    const int m0 = blockIdx.x * TM;
    const int n0 = blockIdx.y * TN;

    float acc[8][8];
#pragma unroll
    for (int r = 0; r < 8; r++)
#pragma unroll
        for (int c = 0; c < 8; c++) acc[r][c] = 0.f;

    for (int k0 = 0; k0 < DD; k0 += TK) {
#pragma unroll
        for (int i = 0; i < 2; i++) {
            int idx = t + i * 256;
            int row = idx >> 2, c4 = idx & 3;
            float4 v = *(const float4*)&g_ln[(size_t)(m0 + row) * DD + k0 + c4 * 4];
            As[c4 * 4 + 0][row] = v.x;
            As[c4 * 4 + 1][row] = v.y;
            As[c4 * 4 + 2][row] = v.z;
            As[c4 * 4 + 3][row] = v.w;
        }
#pragma unroll
        for (int i = 0; i < 2; i++) {
            int idx = t + i * 256;
            int row = idx >> 2, c4 = idx & 3;
            float4 v = *(const float4*)&Wo[(size_t)(n0 + row) * DD + k0 + c4 * 4];
            Bs[c4 * 4 + 0][row] = v.x;
            Bs[c4 * 4 + 1][row] = v.y;
            Bs[c4 * 4 + 2][row] = v.z;
            Bs[c4 * 4 + 3][row] = v.w;
        }
        __syncthreads();

#pragma unroll
        for (int k = 0; k < TK; k++) {
            float4 a0 = *(const float4*)&As[k][ty * 4];
            float4 a1 = *(const float4*)&As[k][64 + ty * 4];
            float4 b0 = *(const float4*)&Bs[k][tx * 4];
            float4 b1 = *(const float4*)&Bs[k][64 + tx * 4];
            float a[8] = {a0.x, a0.y, a0.z, a0.w, a1.x, a1.y, a1.z, a1.w};
            float b[8] = {b0.x, b0.y, b0.z, b0.w, b1.x, b1.y, b1.z, b1.w};
#pragma unroll
            for (int r = 0; r < 8; r++)
#pragma unroll
                for (int c = 0; c < 8; c++) acc[r][c] += a[r] * b[c];
        }
        __syncthreads();
    }

#pragma unroll
    for (int hn = 0; hn < 2; hn++) {
        int col = n0 + hn * 64 + tx * 4;
        float4 bv4 = *(const float4*)&bo[col];
#pragma unroll
        for (int hm = 0; hm < 2; hm++) {
#pragma unroll
            for (int r = 0; r < 4; r++) {
                int m = m0 + hm * 64 + ty * 4 + r;
                float mk = mask[m];     // mask is [B,S] flattened == token index
                float v0 = acc[hm * 4 + r][hn * 4 + 0] + bv4.x;
                float v1 = acc[hm * 4 + r][hn * 4 + 1] + bv4.y;
                float v2 = acc[hm * 4 + r][hn * 4 + 2] + bv4.z;
                float v3 = acc[hm * 4 + r][hn * 4 + 3] + bv4.w;
                v0 = (v0 >= 0.f ? v0 : 0.01f * v0) * mk;
                v1 = (v1 >= 0.f ? v1 : 0.01f * v1) * mk;
                v2 = (v2 >= 0.f ? v2 : 0.01f * v2) * mk;
                v3 = (v3 >= 0.f ? v3 : 0.01f * v3) * mk;
                float4 res = {v0, v1, v2, v3};
                *(float4*)&out[(size_t)m * DD + col] = res;
            }
        }
    }
}

// =========================================================================
// launch
// =========================================================================
extern "C" void kernel_launch(void* const* d_in, const int* in_sizes, int n_in,
                              void* d_out, int out_size)
{
    const float* inputs = (const float*)d_in[0];
    const float* mask   = (const float*)d_in[1];
    const float* Wq = (const float*)d_in[2];
    const float* bq = (const float*)d_in[3];
    const float* Wk = (const float*)d_in[4];
    const float* bk = (const float*)d_in[5];
    const float* Wv = (const float*)d_in[6];
    const float* bv = (const float*)d_in[7];
    const float* Wo = (const float*)d_in[8];
    const float* bo = (const float*)d_in[9];
    const float* ln_g = (const float*)d_in[10];
    const float* ln_b = (const float*)d_in[11];
    float* out = (float*)d_out;

    cudaFuncSetAttribute(attn_kernel, cudaFuncAttributeMaxDynamicSharedMemorySize,
                         ATT_SMEM_BYTES);

    qkv_kernel<<<dim3(NTOK / TM, DD / TN, 3), 256>>>(inputs, Wq, bq, Wk, bk, Wv, bv);
    attn_kernel<<<dim3(SS / 64, BB * HH), 256, ATT_SMEM_BYTES>>>(mask);
    ln_kernel<<<NTOK, 256>>>(inputs, ln_g, ln_b);
    out_kernel<<<dim3(NTOK / TM, DD / TN), 256>>>(Wo, bo, mask, out);
}

// round 3
// speedup vs baseline: 2.6427x; 2.6427x over previous
#include <cuda_runtime.h>
#include <cstdint>

#define BB 4
#define SS 2048
#define DD 1024
#define HH 16
#define HD 64
#define NTOK (BB*SS)          // 8192

// ---------------- scratch (device globals; no allocation) ----------------
__device__ float g_Q[(size_t)BB*HH*SS*HD];     // [B,H,S,HD]
__device__ float g_K[(size_t)BB*HH*SS*HD];
__device__ float g_V[(size_t)BB*HH*SS*HD];
__device__ float g_ctx[(size_t)NTOK*DD];       // [B,S,D]
__device__ float g_ln[(size_t)NTOK*DD];        // [B,S,D]

// ---------------- tf32 mma helpers ----------------
__device__ __forceinline__ uint32_t f2tf(float x) {
    uint32_t u; asm("cvt.rna.tf32.f32 %0, %1;" : "=r"(u) : "f"(x)); return u;
}
__device__ __forceinline__ void mma8(float d[4], const uint32_t a[4], const uint32_t b[2]) {
    asm("mma.sync.aligned.m16n8k8.row.col.f32.tf32.tf32.f32 "
        "{%0,%1,%2,%3}, {%4,%5,%6,%7}, {%8,%9}, {%0,%1,%2,%3};"
        : "+f"(d[0]), "+f"(d[1]), "+f"(d[2]), "+f"(d[3])
        : "r"(a[0]), "r"(a[1]), "r"(a[2]), "r"(a[3]), "r"(b[0]), "r"(b[1]));
}

// Fragment-canonical smem tile strides (padded against bank conflicts)
#define ATS 132   // A-frag tile: 32 lanes * 4 regs + 4 pad  (words)
#define BTS 66    // B-frag tile: 32 lanes * 2 regs + 2 pad  (words)

// =========================================================================
// Kernel 1: fused QKV projection via tf32 mma.  C = X @ W^T + b  -> [B,H,S,HD]
// Tiles 128x128x32, 256 threads (8 warps, 2x4), 64x32 per warp.
// =========================================================================
__global__ __launch_bounds__(256) void qkv_mma(
    const float* __restrict__ X,
    const float* __restrict__ Wq, const float* __restrict__ bq,
    const float* __restrict__ Wk, const float* __restrict__ bk,
    const float* __restrict__ Wv, const float* __restrict__ bv)
{
    const float* W; const float* bias; float* out;
    if (blockIdx.z == 0)      { W = Wq; bias = bq; out = g_Q; }
    else if (blockIdx.z == 1) { W = Wk; bias = bk; out = g_K; }
    else                      { W = Wv; bias = bv; out = g_V; }

    __shared__ uint32_t Af[8 * 4 * ATS];    // 8 m-tiles x 4 k-tiles
    __shared__ uint32_t Bf[16 * 4 * BTS];   // 16 n-tiles x 4 k-tiles

    const int t    = threadIdx.x;
    const int lane = t & 31;
    const int w    = t >> 5;
    const int wm   = w >> 2;        // 0..1
    const int wn   = w & 3;         // 0..3
    const int m0   = blockIdx.x * 128;
    const int n0   = blockIdx.y * 128;

    float acc[4][4][4];
#pragma unroll
    for (int mt = 0; mt < 4; mt++)
#pragma unroll
        for (int nt = 0; nt < 4; nt++)
#pragma unroll
            for (int e = 0; e < 4; e++) acc[mt][nt][e] = 0.f;

    for (int k0 = 0; k0 < DD; k0 += 32) {
        __syncthreads();
        // stage A (X) and B (W) into canonical fragment layout (tf32)
#pragma unroll
        for (int i = 0; i < 4; i++) {
            int idx = t + i * 256;            // 1024 float4s
            int row = idx >> 3;               // 0..127
            int kc  = idx & 7;                // float4 index along k (k = kc*4)
            // ---- A ----
            float4 va = *(const float4*)&X[(size_t)(m0 + row) * DD + k0 + kc * 4];
            int mt = row >> 4, r = row & 15, g = r & 7, hi = r >> 3;
            uint32_t* pa = &Af[(mt * 4 + (kc >> 1)) * ATS + g * 16 + hi + 2 * (kc & 1)];
            pa[0]  = f2tf(va.x); pa[4]  = f2tf(va.y);
            pa[8]  = f2tf(va.z); pa[12] = f2tf(va.w);
            // ---- B ----
            float4 vb = *(const float4*)&W[(size_t)(n0 + row) * DD + k0 + kc * 4];
            int ntl = row >> 3, nn = row & 7;
            uint32_t* pb = &Bf[(ntl * 4 + (kc >> 1)) * BTS + nn * 8 + (kc & 1)];
            pb[0] = f2tf(vb.x); pb[2] = f2tf(vb.y);
            pb[4] = f2tf(vb.z); pb[6] = f2tf(vb.w);
        }
        __syncthreads();

#pragma unroll
        for (int kt = 0; kt < 4; kt++) {
            uint32_t a[4][4], b[4][2];
#pragma unroll
            for (int mt = 0; mt < 4; mt++)
                *(uint4*)a[mt] = *(const uint4*)&Af[((wm * 4 + mt) * 4 + kt) * ATS + lane * 4];
#pragma unroll
            for (int nt = 0; nt < 4; nt++)
                *(uint2*)b[nt] = *(const uint2*)&Bf[((wn * 4 + nt) * 4 + kt) * BTS + lane * 2];
#pragma unroll
            for (int mt = 0; mt < 4; mt++)
#pragma unroll
                for (int nt = 0; nt < 4; nt++)
                    mma8(acc[mt][nt], a[mt], b[nt]);
        }
    }

    // epilogue: bias add, scatter to [B,H,S,HD]
    const int g  = lane >> 2;
    const int qd = lane & 3;
    const int bidx  = m0 >> 11;       // batch (block never straddles batches)
    const int sbase = m0 & (SS - 1);
#pragma unroll
    for (int nt = 0; nt < 4; nt++) {
        int col = n0 + wn * 32 + nt * 8 + qd * 2;
        int h = col >> 6, d = col & 63;
        float bx = bias[col], by = bias[col + 1];
        float* obase = out + ((size_t)(bidx * HH + h) * SS) * HD + d;
#pragma unroll
        for (int mt = 0; mt < 4; mt++) {
            int s = sbase + wm * 64 + mt * 16 + g;
            float2 v0 = {acc[mt][nt][0] + bx, acc[mt][nt][1] + by};
            float2 v1 = {acc[mt][nt][2] + bx, acc[mt][nt][3] + by};
            *(float2*)&obase[(size_t)s * HD]       = v0;
            *(float2*)&obase[(size_t)(s + 8) * HD] = v1;
        }
    }
}

// =========================================================================
// Kernel 2: flash attention via tf32 mma.  grid=(S/64, B*H), 128 threads.
// Each of 4 warps owns 16 q-rows.  QK^T and PV as m16n8k8 mma.
// =========================================================================
// dyn smem (words): Qf 4*8*ATS | Kf 8*8*BTS | Vf 8*8*BTS | Pf 4*8*ATS | Ms 64
#define QF_W (4*8*ATS)
#define KF_W (8*8*BTS)
#define VF_W (8*8*BTS)
#define PF_W (4*8*ATS)
#define ATT_SMEM_BYTES ((QF_W + KF_W + VF_W + PF_W + 64) * 4)

__global__ __launch_bounds__(128) void attn_mma(const float* __restrict__ mask)
{
    extern __shared__ uint32_t smw[];
    uint32_t* Qf = smw;
    uint32_t* Kf = Qf + QF_W;
    uint32_t* Vf = Kf + KF_W;
    uint32_t* Pf = Vf + VF_W;
    float*    Ms = (float*)(Pf + PF_W);

    const int t    = threadIdx.x;
    const int lane = t & 31;
    const int wq   = t >> 5;          // warp -> 16 q-rows
    const int g    = lane >> 2;
    const int qd   = lane & 3;

    const int q0 = blockIdx.x * 64;
    const int bh = blockIdx.y;
    const int b  = bh >> 4;
    const int h  = bh & 15;

    const float* Qb = g_Q + ((size_t)bh * SS + q0) * HD;
    const float* Kb = g_K + (size_t)bh * SS * HD;
    const float* Vb = g_V + (size_t)bh * SS * HD;
    const float* mb = mask + (size_t)b * SS;

    // ---- stage Q tile (64x64) into A-frag layout ----
#pragma unroll
    for (int i = 0; i < 8; i++) {
        int idx = t + i * 128;            // 1024 float4s
        int row = idx >> 4;               // 0..63
        int kc  = idx & 15;               // d = kc*4
        float4 v = *(const float4*)&Qb[(size_t)row * HD + kc * 4];
        int mt = row >> 4, r = row & 15, gg = r & 7, hi = r >> 3;
        uint32_t* p = &Qf[(mt * 8 + (kc >> 1)) * ATS + gg * 16 + hi + 2 * (kc & 1)];
        p[0]  = f2tf(v.x); p[4]  = f2tf(v.y);
        p[8]  = f2tf(v.z); p[12] = f2tf(v.w);
    }

    float mi[2] = {-1e30f, -1e30f};
    float li[2] = {0.f, 0.f};
    float o[8][4];
#pragma unroll
    for (int nt = 0; nt < 8; nt++)
#pragma unroll
        for (int e = 0; e < 4; e++) o[nt][e] = 0.f;

    for (int j = 0; j < SS / 64; j++) {
        const int kv0 = j * 64;
        __syncthreads();
        // ---- stage K (B-frag: n=kv, k=d) and V (B-frag: k=kv, n=d) ----
#pragma unroll
        for (int i = 0; i < 8; i++) {
            int idx = t + i * 128;
            int row = idx >> 4;           // kv row 0..63
            int kc  = idx & 15;           // d = kc*4
            float4 vk = *(const float4*)&Kb[(size_t)(kv0 + row) * HD + kc * 4];
            int ntl = row >> 3, nn = row & 7;
            uint32_t* pk = &Kf[(ntl * 8 + (kc >> 1)) * BTS + nn * 8 + (kc & 1)];
            pk[0] = f2tf(vk.x); pk[2] = f2tf(vk.y);
            pk[4] = f2tf(vk.z); pk[6] = f2tf(vk.w);

            float4 vv = *(const float4*)&Vb[(size_t)(kv0 + row) * HD + kc * 4];
            int kt = row >> 3, kk = row & 7, krem = kk & 3, regv = kk >> 2;
            uint32_t* pv = &Vf[(kt * 8 + (kc >> 1)) * BTS + ((kc & 1) * 16 + krem) * 2 + regv];
            pv[0]  = f2tf(vv.x); pv[8]  = f2tf(vv.y);
            pv[16] = f2tf(vv.z); pv[24] = f2tf(vv.w);
        }
        if (t < 64) Ms[t] = mb[kv0 + t];
        __syncthreads();

        // ---- S = Q K^T ----
        float s[8][4];
#pragma unroll
        for (int nt = 0; nt < 8; nt++)
#pragma unroll
            for (int e = 0; e < 4; e++) s[nt][e] = 0.f;

#pragma unroll
        for (int kt = 0; kt < 8; kt++) {
            uint32_t a[4];
            *(uint4*)a = *(const uint4*)&Qf[(wq * 8 + kt) * ATS + lane * 4];
#pragma unroll
            for (int nt = 0; nt < 8; nt++) {
                uint32_t bf[2];
                *(uint2*)bf = *(const uint2*)&Kf[(nt * 8 + kt) * BTS + lane * 2];
                mma8(s[nt], a, bf);
            }
        }

        // ---- scale + mask + online softmax ----
        float mx0 = -1e30f, mx1 = -1e30f;
#pragma unroll
        for (int nt = 0; nt < 8; nt++) {
#pragma unroll
            for (int e = 0; e < 2; e++) {
                int col = nt * 8 + qd * 2 + e;
                float madd = (1.0f - Ms[col]) * -10000.0f;
                s[nt][e]     = s[nt][e]     * 0.125f + madd;
                s[nt][2 + e] = s[nt][2 + e] * 0.125f + madd;
                mx0 = fmaxf(mx0, s[nt][e]);
                mx1 = fmaxf(mx1, s[nt][2 + e]);
            }
        }
        mx0 = fmaxf(mx0, __shfl_xor_sync(0xffffffffu, mx0, 1));
        mx0 = fmaxf(mx0, __shfl_xor_sync(0xffffffffu, mx0, 2));
        mx1 = fmaxf(mx1, __shfl_xor_sync(0xffffffffu, mx1, 1));
        mx1 = fmaxf(mx1, __shfl_xor_sync(0xffffffffu, mx1, 2));

        float mn0 = fmaxf(mi[0], mx0), mn1 = fmaxf(mi[1], mx1);
        float c0 = __expf(mi[0] - mn0), c1 = __expf(mi[1] - mn1);
        mi[0] = mn0; mi[1] = mn1;

        float rs0 = 0.f, rs1 = 0.f;
#pragma unroll
        for (int nt = 0; nt < 8; nt++) {
#pragma unroll
            for (int e = 0; e < 2; e++) {
                s[nt][e]     = __expf(s[nt][e]     - mn0);
                s[nt][2 + e] = __expf(s[nt][2 + e] - mn1);
                rs0 += s[nt][e];
                rs1 += s[nt][2 + e];
            }
        }
        rs0 += __shfl_xor_sync(0xffffffffu, rs0, 1);
        rs0 += __shfl_xor_sync(0xffffffffu, rs0, 2);
        rs1 += __shfl_xor_sync(0xffffffffu, rs1, 1);
        rs1 += __shfl_xor_sync(0xffffffffu, rs1, 2);
        li[0] = li[0] * c0 + rs0;
        li[1] = li[1] * c1 + rs1;
#pragma unroll
        for (int nt = 0; nt < 8; nt++) {
            o[nt][0] *= c0; o[nt][1] *= c0;
            o[nt][2] *= c1; o[nt][3] *= c1;
        }

        // ---- stage P (warp-private) in A-frag layout ----
#pragma unroll
        for (int nt = 0; nt < 8; nt++) {
#pragma unroll
            for (int e = 0; e < 2; e++) {
                int v2 = qd * 2 + e;
                int c = v2 & 3, ch = v2 >> 2;
                uint32_t* pp = &Pf[(wq * 8 + nt) * ATS + (g * 4 + c) * 4 + 2 * ch];
                pp[0] = f2tf(s[nt][e]);        // row g
                pp[1] = f2tf(s[nt][2 + e]);    // row g+8
            }
        }
        __syncwarp();

        // ---- O += P @ V ----
#pragma unroll
        for (int kt = 0; kt < 8; kt++) {
            uint32_t a[4];
            *(uint4*)a = *(const uint4*)&Pf[(wq * 8 + kt) * ATS + lane * 4];
#pragma unroll
            for (int nt = 0; nt < 8; nt++) {
                uint32_t bf[2];
                *(uint2*)bf = *(const uint2*)&Vf[(kt * 8 + nt) * BTS + lane * 2];
                mma8(o[nt], a, bf);
            }
        }
        __syncwarp();
    }

    // ---- epilogue: normalize, write ctx[b][s][h*64+d] ----
    float inv0 = 1.0f / li[0], inv1 = 1.0f / li[1];
    int row0 = q0 + wq * 16 + g;
    float* cb = g_ctx + (size_t)(b * SS) * DD + h * HD;
#pragma unroll
    for (int nt = 0; nt < 8; nt++) {
        int d = nt * 8 + qd * 2;
        float2 u0 = {o[nt][0] * inv0, o[nt][1] * inv0};
        float2 u1 = {o[nt][2] * inv1, o[nt][3] * inv1};
        *(float2*)&cb[(size_t)row0 * DD + d]       = u0;
        *(float2*)&cb[(size_t)(row0 + 8) * DD + d] = u1;
    }
}

// =========================================================================
// Kernel 3: residual add + LayerNorm, one block per row
// =========================================================================
__device__ __forceinline__ float block_reduce_sum(float v, float* sred)
{
    int t = threadIdx.x;
#pragma unroll
    for (int o = 16; o > 0; o >>= 1) v += __shfl_xor_sync(0xffffffffu, v, o);
    if ((t & 31) == 0) sred[t >> 5] = v;
    __syncthreads();
    if (t < 32) {
        float x = (t < 8) ? sred[t] : 0.f;
#pragma unroll
        for (int o = 4; o > 0; o >>= 1) x += __shfl_xor_sync(0xffffffffu, x, o);
        if (t == 0) sred[0] = x;
    }
    __syncthreads();
    float r = sred[0];
    __syncthreads();
    return r;
}

__global__ __launch_bounds__(256) void ln_kernel(
    const float* __restrict__ resid,
    const float* __restrict__ gamma, const float* __restrict__ beta)
{
    __shared__ float sred[8];
    const int row = blockIdx.x;
    const int t = threadIdx.x;

    float4 c4 = *(const float4*)&g_ctx[(size_t)row * DD + t * 4];
    float4 r4 = *(const float4*)&resid[(size_t)row * DD + t * 4];
    float x0 = c4.x + r4.x, x1 = c4.y + r4.y, x2 = c4.z + r4.z, x3 = c4.w + r4.w;

    float mu = block_reduce_sum(x0 + x1 + x2 + x3, sred) * (1.0f / DD);
    float d0 = x0 - mu, d1 = x1 - mu, d2 = x2 - mu, d3 = x3 - mu;
    float var = block_reduce_sum(d0 * d0 + d1 * d1 + d2 * d2 + d3 * d3, sred) * (1.0f / DD);
    float rstd = rsqrtf(var + 1e-5f);

    float4 g4 = *(const float4*)&gamma[t * 4];
    float4 b4 = *(const float4*)&beta[t * 4];
    float4 res;
    res.x = d0 * rstd * g4.x + b4.x;
    res.y = d1 * rstd * g4.y + b4.y;
    res.z = d2 * rstd * g4.z + b4.z;
    res.w = d3 * rstd * g4.w + b4.w;
    *(float4*)&g_ln[(size_t)row * DD + t * 4] = res;
}

// =========================================================================
// Kernel 4: output GEMM (tf32 mma) + bias + LeakyReLU + mask
// =========================================================================
__global__ __launch_bounds__(256) void out_mma(
    const float* __restrict__ Wo, const float* __restrict__ bo,
    const float* __restrict__ mask, float* __restrict__ out)
{
    __shared__ uint32_t Af[8 * 4 * ATS];
    __shared__ uint32_t Bf[16 * 4 * BTS];

    const int t    = threadIdx.x;
    const int lane = t & 31;
    const int w    = t >> 5;
    const int wm   = w >> 2;
    const int wn   = w & 3;
    const int m0   = blockIdx.x * 128;
    const int n0   = blockIdx.y * 128;

    float acc[4][4][4];
#pragma unroll
    for (int mt = 0; mt < 4; mt++)
#pragma unroll
        for (int nt = 0; nt < 4; nt++)
#pragma unroll
            for (int e = 0; e < 4; e++) acc[mt][nt][e] = 0.f;

    for (int k0 = 0; k0 < DD; k0 += 32) {
        __syncthreads();
#pragma unroll
        for (int i = 0; i < 4; i++) {
            int idx = t + i * 256;
            int row = idx >> 3;
            int kc  = idx & 7;
            float4 va = *(const float4*)&g_ln[(size_t)(m0 + row) * DD + k0 + kc * 4];
            int mt = row >> 4, r = row & 15, g = r & 7, hi = r >> 3;
            uint32_t* pa = &Af[(mt * 4 + (kc >> 1)) * ATS + g * 16 + hi + 2 * (kc & 1)];
            pa[0]  = f2tf(va.x); pa[4]  = f2tf(va.y);
            pa[8]  = f2tf(va.z); pa[12] = f2tf(va.w);

            float4 vb = *(const float4*)&Wo[(size_t)(n0 + row) * DD + k0 + kc * 4];
            int ntl = row >> 3, nn = row & 7;
            uint32_t* pb = &Bf[(ntl * 4 + (kc >> 1)) * BTS + nn * 8 + (kc & 1)];
            pb[0] = f2tf(vb.x); pb[2] = f2tf(vb.y);
            pb[4] = f2tf(vb.z); pb[6] = f2tf(vb.w);
        }
        __syncthreads();

#pragma unroll
        for (int kt = 0; kt < 4; kt++) {
            uint32_t a[4][4], b[4][2];
#pragma unroll
            for (int mt = 0; mt < 4; mt++)
                *(uint4*)a[mt] = *(const uint4*)&Af[((wm * 4 + mt) * 4 + kt) * ATS + lane * 4];
#pragma unroll
            for (int nt = 0; nt < 4; nt++)
                *(uint2*)b[nt] = *(const uint2*)&Bf[((wn * 4 + nt) * 4 + kt) * BTS + lane * 2];
#pragma unroll
            for (int mt = 0; mt < 4; mt++)
#pragma unroll
                for (int nt = 0; nt < 4; nt++)
                    mma8(acc[mt][nt], a[mt], b[nt]);
        }
    }

    const int g  = lane >> 2;
    const int qd = lane & 3;
#pragma unroll
    for (int nt = 0; nt < 4; nt++) {
        int col = n0 + wn * 32 + nt * 8 + qd * 2;
        float bx = bo[col], by = bo[col + 1];
#pragma unroll
        for (int mt = 0; mt < 4; mt++) {
            int row = m0 + wm * 64 + mt * 16 + g;
            float mk0 = mask[row], mk1 = mask[row + 8];
            float v0 = acc[mt][nt][0] + bx;
            float v1 = acc[mt][nt][1] + by;
            float v2 = acc[mt][nt][2] + bx;
            float v3 = acc[mt][nt][3] + by;
            v0 = (v0 >= 0.f ? v0 : 0.01f * v0) * mk0;
            v1 = (v1 >= 0.f ? v1 : 0.01f * v1) * mk0;
            v2 = (v2 >= 0.f ? v2 : 0.01f * v2) * mk1;
            v3 = (v3 >= 0.f ? v3 : 0.01f * v3) * mk1;
            float2 u0 = {v0, v1};
            float2 u1 = {v2, v3};
            *(float2*)&out[(size_t)row * DD + col]       = u0;
            *(float2*)&out[(size_t)(row + 8) * DD + col] = u1;
        }
    }
}

// =========================================================================
// launch
// =========================================================================
extern "C" void kernel_launch(void* const* d_in, const int* in_sizes, int n_in,
                              void* d_out, int out_size)
{
    const float* inputs = (const float*)d_in[0];
    const float* mask   = (const float*)d_in[1];
    const float* Wq = (const float*)d_in[2];
    const float* bq = (const float*)d_in[3];
    const float* Wk = (const float*)d_in[4];
    const float* bk = (const float*)d_in[5];
    const float* Wv = (const float*)d_in[6];
    const float* bv = (const float*)d_in[7];
    const float* Wo = (const float*)d_in[8];
    const float* bo = (const float*)d_in[9];
    const float* ln_g = (const float*)d_in[10];
    const float* ln_b = (const float*)d_in[11];
    float* out = (float*)d_out;

    cudaFuncSetAttribute(attn_mma, cudaFuncAttributeMaxDynamicSharedMemorySize,
                         ATT_SMEM_BYTES);

    qkv_mma<<<dim3(NTOK / 128, DD / 128, 3), 256>>>(inputs, Wq, bq, Wk, bk, Wv, bv);
    attn_mma<<<dim3(SS / 64, BB * HH), 128, ATT_SMEM_BYTES>>>(mask);
    ln_kernel<<<NTOK, 256>>>(inputs, ln_g, ln_b);
    out_mma<<<dim3(NTOK / 128, DD / 128), 256>>>(Wo, bo, mask, out);
}